// round 7
// baseline (speedup 1.0000x reference)
#include <cuda_runtime.h>
#include <math.h>

// BackupBarrierCBF — analytic version.
// For each (b,a) element: relative trajectory in the (time-invariant) ego frame
// is affine in t:  ex_i(t) = X_i + p*t,  ey_i(t) = Y_i + q*t  (slopes p,q shared
// across the 4 corners). Per corner, f(t) = max(|X+pt|-kx, |Y+qt|-ky) is convex
// piecewise-linear; its continuous argmin is at a breakpoint: one of 2 vertices
// or 4 line intersections. Integer min over t in [1,50] is then at floor/ceil of
// the clamped continuous argmin — so we evaluate f at 12 integer points per
// corner instead of rolling out 50 steps.
#define T_LO 1.0f
#define T_HI 50.0f

__global__ __launch_bounds__(128)
void cbf_kernel(const float* __restrict__ data, float* __restrict__ out, int n) {
    int idx = blockIdx.x * blockDim.x + threadIdx.x;
    if (idx >= n) return;

    const float* p15 = data + (size_t)idx * 15;
    float exg  = p15[0],  eyg  = p15[1],  eyaw = p15[2],  ev = p15[3];
    float axg  = p15[4],  ayg  = p15[5],  ayaw = p15[6],  av = p15[7];
    float eL   = p15[8],  eW   = p15[9];
    float aL   = p15[11], aW   = p15[12];
    float dt   = p15[14];

    float se, ce, sa, ca;
    __sincosf(eyaw, &se, &ce);     // yaw in [-pi, pi]; fast path is plenty accurate
    __sincosf(ayaw, &sa, &ca);

    // Relative velocity per step (world), then rotated into the ego frame.
    float dvx = dt * (av * ca - ev * ce);
    float dvy = dt * (av * sa - ev * se);
    float p =  dvx * ce + dvy * se;   // d(ex)/dt-step
    float q = -dvx * se + dvy * ce;   // d(ey)/dt-step

    float rx0 = axg - exg;
    float ry0 = ayg - eyg;

    const float kx = 0.5f * eL + 1.0f;   // OFFSET_X
    const float ky = 0.5f * eW + 0.3f;   // OFFSET_Y
    const float c  = kx - ky;

    float hx = 0.5f * aL, hy = 0.5f * aW;

    // Reciprocals shared across corners. Zero/parallel slopes -> inf/NaN
    // candidates, which clamp harmlessly (fmaxf/fminf drop NaNs).
    float rp  = __fdividef(1.0f, p);
    float rq  = __fdividef(1.0f, q);
    float rd1 = __fdividef(1.0f, p - q);
    float rd2 = __fdividef(1.0f, p + q);

    float hm = 3.4e38f;

    #pragma unroll
    for (int i = 0; i < 4; ++i) {
        float cxv = (i < 2) ? hx : -hx;
        float cyv = (i & 1) ? -hy : hy;
        // Agent corner, world frame, relative to ego, at t=0; then ego frame.
        float ox = rx0 + cxv * ca - cyv * sa;
        float oy = ry0 + cxv * sa + cyv * ca;
        float X  =  ox * ce + oy * se;
        float Y  = -ox * se + oy * ce;

        float s = X + Y, d = Y - X;

        // 6 breakpoint candidates: 2 vertices + 4 sign-pattern intersections.
        float cand[6];
        cand[0] = -X * rp;             // vertex of |X+pt|
        cand[1] = -Y * rq;             // vertex of |Y+qt|
        cand[2] = (d + c) * rd1;       // (+,+):  (X+pt)-kx =  (Y+qt)-ky
        cand[3] = (c - s) * rd2;       // (+,-):  (X+pt)-kx = -(Y+qt)-ky
        cand[4] = -(s + c) * rd2;      // (-,+)
        cand[5] = (d - c) * rd1;       // (-,-)

        #pragma unroll
        for (int j = 0; j < 6; ++j) {
            float tcl = fminf(fmaxf(cand[j], T_LO), T_HI);  // NaN -> T_LO
            float tf  = floorf(tcl);
            float te  = fminf(tf + 1.0f, T_HI);
            // evaluate f at the two integer neighbors
            float x0 = fmaf(p, tf, X), y0 = fmaf(q, tf, Y);
            float m0 = fmaxf(fabsf(x0) - kx, fabsf(y0) - ky);
            float x1 = fmaf(p, te, X), y1 = fmaf(q, te, Y);
            float m1 = fmaxf(fabsf(x1) - kx, fabsf(y1) - ky);
            hm = fminf(hm, fminf(m0, m1));
        }
    }

    // h = (sigmoid(h/5) - 0.5) * 10 = 10/(1+e^{-h/5}) - 5
    out[idx] = __fdividef(10.0f, 1.0f + __expf(-hm * 0.2f)) - 5.0f;
}

extern "C" void kernel_launch(void* const* d_in, const int* in_sizes, int n_in,
                              void* d_out, int out_size) {
    const float* data = (const float*)d_in[0];
    float* out = (float*)d_out;
    int n = out_size;                  // B*A = 131072
    int threads = 128;
    int blocks = (n + threads - 1) / threads;  // 1024 blocks -> good wave balance
    cbf_kernel<<<blocks, threads>>>(data, out, n);
}

// round 8
// speedup vs baseline: 1.5953x; 1.5953x over previous
#include <cuda_runtime.h>
#include <math.h>

// BackupBarrierCBF — closed-form per-corner argmin.
// Ego-frame relative corner position is affine in t: (X+pt, Y+qt), slopes p,q
// shared by all 4 corners. f(t) = max(|X+pt|-kx, |Y+qt|-ky) is a max of two
// V-shapes; its continuous minimizer is t1, t2 (the vertices) or their unique
// crossing — selected by two comparisons. Discrete argmin over t in [1,50] is
// then floor/ceil of the clamped continuous argmin (convexity), so we evaluate
// f at just 2 integer points per corner.
#define T_LO 1.0f
#define T_HI 50.0f

__global__ __launch_bounds__(128)
void cbf_kernel(const float* __restrict__ data, float* __restrict__ out, int n) {
    int idx = blockIdx.x * blockDim.x + threadIdx.x;
    if (idx >= n) return;

    const float* pp = data + (size_t)idx * 15;
    float exg  = pp[0],  eyg  = pp[1],  eyaw = pp[2],  ev = pp[3];
    float axg  = pp[4],  ayg  = pp[5],  ayaw = pp[6],  av = pp[7];
    float eL   = pp[8],  eW   = pp[9];
    float aL   = pp[11], aW   = pp[12];
    float dt   = pp[14];

    float se, ce, sa, ca;
    __sincosf(eyaw, &se, &ce);
    __sincosf(ayaw, &sa, &ca);

    // Relative velocity per step, rotated into the (time-invariant) ego frame.
    float dvx = dt * (av * ca - ev * ce);
    float dvy = dt * (av * sa - ev * se);
    float p   =  dvx * ce + dvy * se;
    float q   = -dvx * se + dvy * ce;
    float ap  = fabsf(p), aq = fabsf(q);
    float rp  = __fdividef(1.0f, p);
    float rq  = __fdividef(1.0f, q);
    float rs  = __fdividef(1.0f, ap + aq);

    // Relative center at t=0, ego frame.
    float rx0 = axg - exg, ry0 = ayg - eyg;
    float Xc  =  rx0 * ce + ry0 * se;
    float Yc  = -rx0 * se + ry0 * ce;

    // Agent box half-axes expressed in the ego frame (rotation by ayaw-eyaw).
    float cd = ca * ce + sa * se;   // cos(ayaw - eyaw)
    float sd = sa * ce - ca * se;   // sin(ayaw - eyaw)
    float hx = 0.5f * aL, hy = 0.5f * aW;
    float ux =  hx * cd, uy = hx * sd;
    float vx = -hy * sd, vy = hy * cd;

    const float kx  = 0.5f * eL + 1.0f;   // OFFSET_X
    const float ky  = 0.5f * eW + 0.3f;   // OFFSET_Y
    const float cdk = kx - ky;
    const float nkx = -kx, nky = -ky;

    float hm = 3.4e38f;

    #pragma unroll
    for (int i = 0; i < 4; ++i) {
        // Corner (sx,sy) in {(+,+),(+,-),(-,+),(-,-)}; signs fold at compile time.
        float X = (i < 2) ? (Xc + ux) : (Xc - ux);
        float Y = (i < 2) ? (Yc + uy) : (Yc - uy);
        if (i & 1) { X -= vx; Y -= vy; } else { X += vx; Y += vy; }

        float t1 = -X * rp;                       // vertex of |X+pt|
        float t2 = -Y * rq;                       // vertex of |Y+qt|
        float g2t1 = fabsf(fmaf(q, t1, Y)) + nky; // g2 at t1
        float g1t2 = fabsf(fmaf(p, t2, X)) + nkx; // g1 at t2

        // Crossing of the two V-shapes between the vertices.
        float csn  = (t2 >= t1) ? cdk : -cdk;
        float tint = fmaf(ap, t1, fmaf(aq, t2, csn)) * rs;

        // Closed-form continuous argmin (NaN comparisons fall through safely).
        float ts = (g2t1 <= nkx) ? t1 : ((g1t2 <= nky) ? t2 : tint);
        ts = fminf(fmaxf(ts, T_LO), T_HI);        // NaN -> T_LO

        float tf = floorf(ts);
        float te = fminf(tf + 1.0f, T_HI);
        float m0 = fmaxf(fabsf(fmaf(p, tf, X)) + nkx,
                         fabsf(fmaf(q, tf, Y)) + nky);
        float m1 = fmaxf(fabsf(fmaf(p, te, X)) + nkx,
                         fabsf(fmaf(q, te, Y)) + nky);
        hm = fminf(hm, fminf(m0, m1));
    }

    // h = (sigmoid(h/5) - 0.5) * 10 = 10/(1+e^{-h/5}) - 5
    out[idx] = __fdividef(10.0f, 1.0f + __expf(-hm * 0.2f)) - 5.0f;
}

extern "C" void kernel_launch(void* const* d_in, const int* in_sizes, int n_in,
                              void* d_out, int out_size) {
    const float* data = (const float*)d_in[0];
    float* out = (float*)d_out;
    int n = out_size;                  // B*A = 131072
    int threads = 128;
    int blocks = (n + threads - 1) / threads;   // 1024 blocks, whole grid resident
    cbf_kernel<<<blocks, threads>>>(data, out, n);
}

// round 9
// speedup vs baseline: 1.6490x; 1.0337x over previous
#include <cuda_runtime.h>
#include <math.h>

// BackupBarrierCBF — closed-form argmin + smem-staged coalesced loads +
// 2-threads-per-element corner split (occupancy 2x, shorter per-thread chain).
#define T_LO 1.0f
#define T_HI 50.0f

#define THREADS 256
#define ELEMS_PER_BLOCK 128           // THREADS / 2
#define FLOATS_PER_BLOCK (ELEMS_PER_BLOCK * 15)   // 1920 floats = 480 float4

__global__ __launch_bounds__(THREADS)
void cbf_kernel(const float* __restrict__ data, float* __restrict__ out, int n) {
    __shared__ float sm[FLOATS_PER_BLOCK];

    int e0 = blockIdx.x * ELEMS_PER_BLOCK;

    // Stage this block's 128 elements: perfectly coalesced float4 loads.
    // e0*15*4 bytes is 16B-aligned (128*15*4 = 7680 per block).
    {
        const float4* g4 = (const float4*)(data + (size_t)e0 * 15);
        float4* s4 = (float4*)sm;
        #pragma unroll
        for (int i = threadIdx.x; i < FLOATS_PER_BLOCK / 4; i += THREADS)
            s4[i] = g4[i];
    }
    __syncthreads();

    int e    = threadIdx.x >> 1;       // element within block (0..127)
    int half = threadIdx.x & 1;        // 0 -> corners {+u±v}, 1 -> {-u±v}
    int gidx = e0 + e;
    if (gidx >= n) return;

    const float* pp = sm + e * 15;     // LDS: 16 distinct banks, pair-broadcast
    float exg  = pp[0],  eyg  = pp[1],  eyaw = pp[2],  ev = pp[3];
    float axg  = pp[4],  ayg  = pp[5],  ayaw = pp[6],  av = pp[7];
    float eL   = pp[8],  eW   = pp[9];
    float aL   = pp[11], aW   = pp[12];
    float dt   = pp[14];

    float se, ce, sa, ca;
    __sincosf(eyaw, &se, &ce);
    __sincosf(ayaw, &sa, &ca);

    // Relative velocity per step, rotated into the (time-invariant) ego frame.
    float dvx = dt * (av * ca - ev * ce);
    float dvy = dt * (av * sa - ev * se);
    float p   =  dvx * ce + dvy * se;
    float q   = -dvx * se + dvy * ce;
    float ap  = fabsf(p), aq = fabsf(q);
    float rp  = __fdividef(1.0f, p);
    float rq  = __fdividef(1.0f, q);
    float rs  = __fdividef(1.0f, ap + aq);

    // Relative center at t=0, ego frame.
    float rx0 = axg - exg, ry0 = ayg - eyg;
    float Xc  =  rx0 * ce + ry0 * se;
    float Yc  = -rx0 * se + ry0 * ce;

    // Agent box half-axes in the ego frame (rotation by ayaw - eyaw).
    float cd = ca * ce + sa * se;
    float sd = sa * ce - ca * se;
    float hx = 0.5f * aL, hy = 0.5f * aW;
    float ux =  hx * cd, uy = hx * sd;
    float vx = -hy * sd, vy = hy * cd;

    const float kx  = 0.5f * eL + 1.0f;   // OFFSET_X
    const float ky  = 0.5f * eW + 0.3f;   // OFFSET_Y
    const float cdk = kx - ky;
    const float nkx = -kx, nky = -ky;

    // This thread's corner-pair base: +u for half==0, -u for half==1.
    float su = (half == 0) ? 1.0f : -1.0f;
    float Xb = fmaf(su, ux, Xc);
    float Yb = fmaf(su, uy, Yc);

    float hm = 3.4e38f;

    #pragma unroll
    for (int j = 0; j < 2; ++j) {
        float X = (j == 0) ? (Xb + vx) : (Xb - vx);
        float Y = (j == 0) ? (Yb + vy) : (Yb - vy);

        float t1 = -X * rp;                        // vertex of |X+pt|
        float t2 = -Y * rq;                        // vertex of |Y+qt|
        float g2t1 = fabsf(fmaf(q, t1, Y)) + nky;  // g2 at t1
        float g1t2 = fabsf(fmaf(p, t2, X)) + nkx;  // g1 at t2

        // Crossing of the two V-shapes between the vertices.
        float csn  = (t2 >= t1) ? cdk : -cdk;
        float tint = fmaf(ap, t1, fmaf(aq, t2, csn)) * rs;

        // Closed-form continuous argmin (NaN comparisons fall through safely).
        float ts = (g2t1 <= nkx) ? t1 : ((g1t2 <= nky) ? t2 : tint);
        ts = fminf(fmaxf(ts, T_LO), T_HI);         // NaN -> T_LO

        float tf = floorf(ts);
        float te = fminf(tf + 1.0f, T_HI);
        float m0 = fmaxf(fabsf(fmaf(p, tf, X)) + nkx,
                         fabsf(fmaf(q, tf, Y)) + nky);
        float m1 = fmaxf(fabsf(fmaf(p, te, X)) + nkx,
                         fabsf(fmaf(q, te, Y)) + nky);
        hm = fminf(hm, fminf(m0, m1));
    }

    // Combine the two corner-pairs (lanes 2k and 2k+1 hold the same element).
    hm = fminf(hm, __shfl_xor_sync(0xffffffffu, hm, 1));

    if (half == 0) {
        // h = (sigmoid(h/5) - 0.5) * 10 = 10/(1+e^{-h/5}) - 5
        out[gidx] = __fdividef(10.0f, 1.0f + __expf(-hm * 0.2f)) - 5.0f;
    }
}

extern "C" void kernel_launch(void* const* d_in, const int* in_sizes, int n_in,
                              void* d_out, int out_size) {
    const float* data = (const float*)d_in[0];
    float* out = (float*)d_out;
    int n = out_size;                  // B*A = 131072
    int blocks = (n + ELEMS_PER_BLOCK - 1) / ELEMS_PER_BLOCK;   // 1024
    cbf_kernel<<<blocks, THREADS>>>(data, out, n);
}

// round 10
// speedup vs baseline: 1.6570x; 1.0048x over previous
#include <cuda_runtime.h>
#include <math.h>

// BackupBarrierCBF — closed-form per-corner argmin, 1 thread/element,
// coalesced float4 smem staging, tanh.approx epilogue.
#define T_LO 1.0f
#define T_HI 50.0f

#define THREADS 128
#define ELEMS_PER_BLOCK 128
#define FLOATS_PER_BLOCK (ELEMS_PER_BLOCK * 15)   // 1920 floats = 480 float4

__device__ __forceinline__ float tanh_approx(float x) {
    float y;
    asm("tanh.approx.f32 %0, %1;" : "=f"(y) : "f"(x));
    return y;
}

__global__ __launch_bounds__(THREADS)
void cbf_kernel(const float* __restrict__ data, float* __restrict__ out, int n) {
    __shared__ float sm[FLOATS_PER_BLOCK];

    int e0 = blockIdx.x * ELEMS_PER_BLOCK;

    // Stage 128 elements = 480 float4: fully coalesced (block base is 16B-aligned:
    // 128*15*4 = 7680 bytes per block).
    {
        const float4* g4 = (const float4*)(data + (size_t)e0 * 15);
        float4* s4 = (float4*)sm;
        #pragma unroll
        for (int i = threadIdx.x; i < FLOATS_PER_BLOCK / 4; i += THREADS)
            s4[i] = g4[i];
    }
    __syncthreads();

    int e = threadIdx.x;               // one element per thread
    const float* pp = sm + e * 15;     // stride 15 words: 32 distinct banks/warp
    float exg  = pp[0],  eyg  = pp[1],  eyaw = pp[2],  ev = pp[3];
    float axg  = pp[4],  ayg  = pp[5],  ayaw = pp[6],  av = pp[7];
    float eL   = pp[8],  eW   = pp[9];
    float aL   = pp[11], aW   = pp[12];
    float dt   = pp[14];

    float se, ce, sa, ca;
    __sincosf(eyaw, &se, &ce);
    __sincosf(ayaw, &sa, &ca);

    // Relative velocity per step, rotated into the (time-invariant) ego frame.
    float dvx = dt * (av * ca - ev * ce);
    float dvy = dt * (av * sa - ev * se);
    float p   =  dvx * ce + dvy * se;
    float q   = -dvx * se + dvy * ce;
    float ap  = fabsf(p), aq = fabsf(q);
    float rp  = __fdividef(1.0f, p);
    float rq  = __fdividef(1.0f, q);
    float rs  = __fdividef(1.0f, ap + aq);

    // Relative center at t=0, ego frame.
    float rx0 = axg - exg, ry0 = ayg - eyg;
    float Xc  =  rx0 * ce + ry0 * se;
    float Yc  = -rx0 * se + ry0 * ce;

    // Agent box half-axes in the ego frame (rotation by ayaw - eyaw).
    float cd = ca * ce + sa * se;
    float sd = sa * ce - ca * se;
    float hx = 0.5f * aL, hy = 0.5f * aW;
    float ux =  hx * cd, uy = hx * sd;
    float vx = -hy * sd, vy = hy * cd;

    const float kx  = 0.5f * eL + 1.0f;   // OFFSET_X
    const float ky  = 0.5f * eW + 0.3f;   // OFFSET_Y
    const float cdk = kx - ky;
    const float nkx = -kx, nky = -ky;

    // 4 independent per-corner min accumulators (ILP), tree-combined at the end.
    float hacc[4];

    #pragma unroll
    for (int i = 0; i < 4; ++i) {
        float X = (i < 2) ? (Xc + ux) : (Xc - ux);
        float Y = (i < 2) ? (Yc + uy) : (Yc - uy);
        if (i & 1) { X -= vx; Y -= vy; } else { X += vx; Y += vy; }

        float t1 = -X * rp;                        // vertex of |X+pt|
        float t2 = -Y * rq;                        // vertex of |Y+qt|
        float g2t1 = fabsf(fmaf(q, t1, Y)) + nky;  // g2 at t1
        float g1t2 = fabsf(fmaf(p, t2, X)) + nkx;  // g1 at t2

        // Crossing of the two V-shapes between the vertices.
        float csn  = (t2 >= t1) ? cdk : -cdk;
        float tint = fmaf(ap, t1, fmaf(aq, t2, csn)) * rs;

        // Closed-form continuous argmin (NaN comparisons fall through safely).
        float ts = (g2t1 <= nkx) ? t1 : ((g1t2 <= nky) ? t2 : tint);
        ts = fminf(fmaxf(ts, T_LO), T_HI);         // NaN -> T_LO

        float tf = floorf(ts);
        float te = fminf(tf + 1.0f, T_HI);
        float m0 = fmaxf(fabsf(fmaf(p, tf, X)) + nkx,
                         fabsf(fmaf(q, tf, Y)) + nky);
        float m1 = fmaxf(fabsf(fmaf(p, te, X)) + nkx,
                         fabsf(fmaf(q, te, Y)) + nky);
        hacc[i] = fminf(m0, m1);
    }

    float hm = fminf(fminf(hacc[0], hacc[1]), fminf(hacc[2], hacc[3]));

    // (sigmoid(h/5) - 0.5) * 10 == 5 * tanh(h/10)  — single MUFU.
    out[e0 + e] = 5.0f * tanh_approx(hm * 0.1f);
}

extern "C" void kernel_launch(void* const* d_in, const int* in_sizes, int n_in,
                              void* d_out, int out_size) {
    const float* data = (const float*)d_in[0];
    float* out = (float*)d_out;
    int n = out_size;                  // B*A = 131072
    int blocks = (n + ELEMS_PER_BLOCK - 1) / ELEMS_PER_BLOCK;   // 1024
    cbf_kernel<<<blocks, THREADS>>>(data, out, n);
}